// round 2
// baseline (speedup 1.0000x reference)
#include <cuda_runtime.h>
#include <math.h>

#define B_SZ   1024
#define IN_DIM 2048
#define H_DIM  2048
#define KBLK   16
#define HB     128
#define G4H    8192   // 4*H

// ---------------- device scratch (no allocations allowed) ----------------
static __device__ float g_gates[B_SZ * G4H];     // 32 MB: gates [1024, 8192]
static __device__ float g_s[B_SZ * HB];          // 512 KB: per-batch block sum s[b, j]
static __device__ float g_t[B_SZ * 4 * HB];      // 2 MB:  t[b, g*128+i] = Bm[g] @ s[b]
static __device__ float g_C[4 * HB * HB];        // 256 KB: C[g] = A[g] - Bm[g]

// ---------------- small prep kernels ----------------

// s[b, j] = sum_kb h_prev[b, kb*128 + j]
__global__ void sum_blocks_kernel(const float* __restrict__ h_prev) {
    int b = blockIdx.x;
    int j = threadIdx.x;
    const float* hp = h_prev + (size_t)b * H_DIM + j;
    float acc = 0.f;
#pragma unroll
    for (int kb = 0; kb < KBLK; ++kb) acc += hp[kb * HB];
    g_s[b * HB + j] = acc;
}

// C = A - Bm (elementwise over 4*128*128)
__global__ void make_C_kernel(const float* __restrict__ A, const float* __restrict__ Bm) {
    int i = blockIdx.x * blockDim.x + threadIdx.x;
    g_C[i] = A[i] - Bm[i];
}

// ---------------- generic tiled NT GEMM: C[m,n] = sum_k A[m,k] * B[n,k] ----------------
// BM = BN = 128, BK = 16, 256 threads, 8x8 per thread.
__global__ __launch_bounds__(256, 2)
void gemm_nt_kernel(const float* __restrict__ A, const float* __restrict__ B,
                    float* __restrict__ C,
                    int K, int lda, int ldb, int ldc) {
    __shared__ float As[16][128];
    __shared__ float Bs[16][128];

    const int m0 = blockIdx.y * 128;
    const int n0 = blockIdx.x * 128;
    const int tid = threadIdx.x;
    const int tx = tid & 15;   // n direction (8 cols each)
    const int ty = tid >> 4;   // m direction (8 rows each)

    float acc[8][8];
#pragma unroll
    for (int u = 0; u < 8; ++u)
#pragma unroll
        for (int v = 0; v < 8; ++v) acc[u][v] = 0.f;

    for (int k0 = 0; k0 < K; k0 += 16) {
#pragma unroll
        for (int l = 0; l < 2; ++l) {
            int f  = tid + l * 256;        // 0..511 float4 slots
            int r  = f >> 2;               // tile row 0..127
            int c4 = (f & 3) * 4;          // k offset {0,4,8,12}
            float4 va = *(const float4*)(A + (size_t)(m0 + r) * lda + k0 + c4);
            As[c4 + 0][r] = va.x; As[c4 + 1][r] = va.y;
            As[c4 + 2][r] = va.z; As[c4 + 3][r] = va.w;
            float4 vb = *(const float4*)(B + (size_t)(n0 + r) * ldb + k0 + c4);
            Bs[c4 + 0][r] = vb.x; Bs[c4 + 1][r] = vb.y;
            Bs[c4 + 2][r] = vb.z; Bs[c4 + 3][r] = vb.w;
        }
        __syncthreads();

#pragma unroll
        for (int kk = 0; kk < 16; ++kk) {
            float a[8], b[8];
            *(float4*)&a[0] = *(const float4*)&As[kk][ty * 8];
            *(float4*)&a[4] = *(const float4*)&As[kk][ty * 8 + 4];
            *(float4*)&b[0] = *(const float4*)&Bs[kk][tx * 8];
            *(float4*)&b[4] = *(const float4*)&Bs[kk][tx * 8 + 4];
#pragma unroll
            for (int u = 0; u < 8; ++u)
#pragma unroll
                for (int v = 0; v < 8; ++v) acc[u][v] += a[u] * b[v];
        }
        __syncthreads();
    }

#pragma unroll
    for (int u = 0; u < 8; ++u) {
        float* crow = C + (size_t)(m0 + ty * 8 + u) * ldc + n0 + tx * 8;
#pragma unroll
        for (int v4 = 0; v4 < 2; ++v4) {
            float4 o;
            o.x = acc[u][v4 * 4 + 0]; o.y = acc[u][v4 * 4 + 1];
            o.z = acc[u][v4 * 4 + 2]; o.w = acc[u][v4 * 4 + 3];
            *(float4*)(crow + v4 * 4) = o;
        }
    }
}

// ---------------- structured block term ----------------
// View h_prev as hp2[16384, 128] (rows = (b, kb)).
// gates[b, g*2048 + kb*128 + i] += sum_j C[g][i][j] * hp2[b*16+kb][j] + t[b, g*128 + i]
__global__ __launch_bounds__(256, 2)
void struct_gemm_kernel(const float* __restrict__ h_prev) {
    const int g  = blockIdx.y;
    const float* A  = h_prev;                    // [16384, 128], lda = 128
    const float* Bw = g_C + g * (HB * HB);       // [128, 128],   ldb = 128

    __shared__ float As[16][128];
    __shared__ float Bs[16][128];

    const int m0 = blockIdx.x * 128;
    const int tid = threadIdx.x;
    const int tx = tid & 15;
    const int ty = tid >> 4;

    float acc[8][8];
#pragma unroll
    for (int u = 0; u < 8; ++u)
#pragma unroll
        for (int v = 0; v < 8; ++v) acc[u][v] = 0.f;

    for (int k0 = 0; k0 < 128; k0 += 16) {
#pragma unroll
        for (int l = 0; l < 2; ++l) {
            int f  = tid + l * 256;
            int r  = f >> 2;
            int c4 = (f & 3) * 4;
            float4 va = *(const float4*)(A + (size_t)(m0 + r) * 128 + k0 + c4);
            As[c4 + 0][r] = va.x; As[c4 + 1][r] = va.y;
            As[c4 + 2][r] = va.z; As[c4 + 3][r] = va.w;
            float4 vb = *(const float4*)(Bw + (size_t)r * 128 + k0 + c4);
            Bs[c4 + 0][r] = vb.x; Bs[c4 + 1][r] = vb.y;
            Bs[c4 + 2][r] = vb.z; Bs[c4 + 3][r] = vb.w;
        }
        __syncthreads();

#pragma unroll
        for (int kk = 0; kk < 16; ++kk) {
            float a[8], b[8];
            *(float4*)&a[0] = *(const float4*)&As[kk][ty * 8];
            *(float4*)&a[4] = *(const float4*)&As[kk][ty * 8 + 4];
            *(float4*)&b[0] = *(const float4*)&Bs[kk][tx * 8];
            *(float4*)&b[4] = *(const float4*)&Bs[kk][tx * 8 + 4];
#pragma unroll
            for (int u = 0; u < 8; ++u)
#pragma unroll
                for (int v = 0; v < 8; ++v) acc[u][v] += a[u] * b[v];
        }
        __syncthreads();
    }

#pragma unroll
    for (int u = 0; u < 8; ++u) {
        int m  = m0 + ty * 8 + u;
        int b  = m >> 4;          // batch
        int kb = m & 15;          // block index
        float* gp       = g_gates + (size_t)b * G4H + g * H_DIM + kb * HB + tx * 8;
        const float* tp = g_t + (size_t)b * (4 * HB) + g * HB + tx * 8;
#pragma unroll
        for (int v = 0; v < 8; ++v)
            gp[v] += acc[u][v] + tp[v];
    }
}

// ---------------- elementwise LSTM epilogue ----------------
__global__ void lstm_elem_kernel(const float* __restrict__ c_prev, float* __restrict__ out) {
    int t = blockIdx.x * blockDim.x + threadIdx.x;   // 0 .. B*H-1
    int b = t >> 11;
    int j = t & (H_DIM - 1);
    const float* Gp = g_gates + (size_t)b * G4H + j;
    float gi = Gp[0];
    float gf = Gp[H_DIM];
    float gg = Gp[2 * H_DIM];
    float go = Gp[3 * H_DIM];

    float i_ = 1.f / (1.f + expf(-gi));
    float f_ = 1.f / (1.f + expf(-gf));
    float g_ = tanhf(gg);
    float o_ = 1.f / (1.f + expf(-go));

    float c = f_ * c_prev[t] + i_ * g_;
    float h = o_ * tanhf(c);

    out[t] = h;                      // h_new
    out[B_SZ * H_DIM + t] = c;       // c
}

// ---------------- launch ----------------
extern "C" void kernel_launch(void* const* d_in, const int* in_sizes, int n_in,
                              void* d_out, int out_size) {
    const float* x      = (const float*)d_in[0];   // [1024, 2048]
    const float* h_prev = (const float*)d_in[1];   // [1024, 2048]
    const float* c_prev = (const float*)d_in[2];   // [1024, 2048]
    const float* Win    = (const float*)d_in[3];   // [8192, 2048]
    const float* A      = (const float*)d_in[4];   // [4, 128, 128]
    const float* Bm     = (const float*)d_in[5];   // [4, 128, 128]
    float* out = (float*)d_out;

    void *p_gates, *p_s, *p_t;
    cudaGetSymbolAddress(&p_gates, g_gates);
    cudaGetSymbolAddress(&p_s, g_s);
    cudaGetSymbolAddress(&p_t, g_t);

    // 1) per-batch block sum s
    sum_blocks_kernel<<<B_SZ, HB>>>(h_prev);

    // 2) C = A - Bm
    make_C_kernel<<<64, 1024>>>(A, Bm);

    // 3) t = s @ Bm^T  : [1024,128] x [512,128]^T -> [1024,512]
    {
        dim3 grid(512 / 128, B_SZ / 128);
        gemm_nt_kernel<<<grid, 256>>>((const float*)p_s, Bm, (float*)p_t,
                                      /*K=*/HB, /*lda=*/HB, /*ldb=*/HB, /*ldc=*/4 * HB);
    }

    // 4) gates = x @ Win^T : [1024,2048] x [8192,2048]^T -> [1024,8192]
    {
        dim3 grid(G4H / 128, B_SZ / 128);
        gemm_nt_kernel<<<grid, 256>>>(x, Win, (float*)p_gates,
                                      /*K=*/IN_DIM, /*lda=*/IN_DIM, /*ldb=*/IN_DIM, /*ldc=*/G4H);
    }

    // 5) gates += hp_blocks @ (A-Bm)^T + broadcast(t)
    {
        dim3 grid((B_SZ * KBLK) / 128, 4);
        struct_gemm_kernel<<<grid, 256>>>(h_prev);
    }

    // 6) elementwise LSTM cell
    lstm_elem_kernel<<<(B_SZ * H_DIM) / 256, 256>>>(c_prev, out);
}

// round 4
// speedup vs baseline: 2.2550x; 2.2550x over previous
#include <cuda_runtime.h>
#include <math.h>
#include <stdint.h>

#define B_SZ   1024
#define IN_DIM 2048
#define H_DIM  2048
#define KBLK   16
#define HB     128
#define G4H    8192   // 4*H

// ---------------- device scratch (no allocations allowed) ----------------
static __device__ float g_gates[B_SZ * G4H];       // 32 MB: gates [1024, 8192]
static __device__ float g_s[B_SZ * HB];            // 512 KB
static __device__ float g_t[B_SZ * 4 * HB];        // 2 MB
static __device__ float g_C[4 * HB * HB];          // 256 KB
static __device__ float g_x32[B_SZ * IN_DIM];      // 8 MB: x rounded to tf32
static __device__ float g_w32[G4H * IN_DIM];       // 64 MB: Win rounded to tf32

// ---------------- helpers ----------------
__device__ __forceinline__ uint32_t smem_u32(const void* p) {
    uint32_t a;
    asm("{ .reg .u64 t; cvta.to.shared.u64 t, %1; cvt.u32.u64 %0, t; }" : "=r"(a) : "l"(p));
    return a;
}
__device__ __forceinline__ void cp16(uint32_t dst, const void* src) {
    asm volatile("cp.async.cg.shared.global [%0], [%1], 16;" :: "r"(dst), "l"(src));
}
#define CP_COMMIT() asm volatile("cp.async.commit_group;" ::: "memory")

__device__ __forceinline__ void mma8(float* c, const uint32_t* a, uint32_t b0, uint32_t b1) {
    asm volatile(
        "mma.sync.aligned.m16n8k8.row.col.f32.tf32.tf32.f32 "
        "{%0,%1,%2,%3}, {%4,%5,%6,%7}, {%8,%9}, {%0,%1,%2,%3};"
        : "+f"(c[0]), "+f"(c[1]), "+f"(c[2]), "+f"(c[3])
        : "r"(a[0]), "r"(a[1]), "r"(a[2]), "r"(a[3]), "r"(b0), "r"(b1));
}

// ---------------- tf32 rounding pre-pass ----------------
__global__ void conv_tf32_kernel(const float* __restrict__ in, float* __restrict__ out) {
    int i = blockIdx.x * blockDim.x + threadIdx.x;
    float4 v = ((const float4*)in)[i];
    uint32_t a, b, c, d;
    asm("cvt.rna.tf32.f32 %0, %1;" : "=r"(a) : "f"(v.x));
    asm("cvt.rna.tf32.f32 %0, %1;" : "=r"(b) : "f"(v.y));
    asm("cvt.rna.tf32.f32 %0, %1;" : "=r"(c) : "f"(v.z));
    asm("cvt.rna.tf32.f32 %0, %1;" : "=r"(d) : "f"(v.w));
    float4 o;
    o.x = __uint_as_float(a); o.y = __uint_as_float(b);
    o.z = __uint_as_float(c); o.w = __uint_as_float(d);
    ((float4*)out)[i] = o;
}

// ---------------- main tensor GEMM via mma.sync tf32 ----------------
// gates[m, n] = sum_k x32[m, k] * w32[n, k]
// CTA tile 128x128, BK=32, double-buffered cp.async. 8 warps = 4(m) x 2(n),
// warp tile 32x64 -> 2 m16 tiles x 8 n8 tiles of m16n8k8 HMMA.
#define BM 128
#define BN 128
#define BKT 32
#define AROW 36                   // BK + 4 pad (floats)
#define ASTG (BM * AROW)          // floats per A stage
#define BSTG (BN * AROW)
#define GSMEM_BYTES ((2 * ASTG + 2 * BSTG) * 4)   // 73728

__global__ __launch_bounds__(256, 1)
void gemm_mma_kernel(const float* __restrict__ X, const float* __restrict__ W) {
    extern __shared__ float sm[];
    float* sA = sm;                // [2][BM][AROW]
    float* sB = sm + 2 * ASTG;     // [2][BN][AROW]

    const int tid  = threadIdx.x;
    const int m0   = blockIdx.y * BM;
    const int n0   = blockIdx.x * BN;
    const int wid  = tid >> 5, lane = tid & 31;
    const int g    = lane >> 2, tg = lane & 3;
    const int wm   = wid & 3;      // m warp 0..3 (32 rows each)
    const int wn   = wid >> 2;     // n warp 0..1 (64 cols each)

    float acc[2][8][4];
#pragma unroll
    for (int mt = 0; mt < 2; ++mt)
#pragma unroll
        for (int nt = 0; nt < 8; ++nt)
#pragma unroll
            for (int q = 0; q < 4; ++q) acc[mt][nt][q] = 0.f;

    const float* Xb = X + (size_t)m0 * IN_DIM;
    const float* Wb = W + (size_t)n0 * IN_DIM;
    const uint32_t sAa = smem_u32(sA);
    const uint32_t sBa = smem_u32(sB);

    auto load = [&](int it) {
        const int s = it & 1;
        const int k0 = it * BKT;
#pragma unroll
        for (int j = 0; j < 4; ++j) {              // A: 128 rows x 8 x 16B
            int c = tid + j * 256;
            int row = c >> 3, kc = c & 7;
            cp16(sAa + (s * ASTG + row * AROW + kc * 4) * 4,
                 Xb + (size_t)row * IN_DIM + k0 + kc * 4);
        }
#pragma unroll
        for (int j = 0; j < 4; ++j) {              // B: 128 rows x 8 x 16B
            int c = tid + j * 256;
            int row = c >> 3, kc = c & 7;
            cp16(sBa + (s * BSTG + row * AROW + kc * 4) * 4,
                 Wb + (size_t)row * IN_DIM + k0 + kc * 4);
        }
        CP_COMMIT();
    };

    const int KITERS = IN_DIM / BKT;   // 64
    load(0);

    for (int it = 0; it < KITERS; ++it) {
        if (it + 1 < KITERS) {
            load(it + 1);
            asm volatile("cp.async.wait_group 1;" ::: "memory");
        } else {
            asm volatile("cp.async.wait_group 0;" ::: "memory");
        }
        __syncthreads();

        const float* A_s = sA + (it & 1) * ASTG;
        const float* B_s = sB + (it & 1) * BSTG;

#pragma unroll
        for (int ks = 0; ks < 4; ++ks) {
            const int k = ks * 8 + tg;
            uint32_t a[2][4];
#pragma unroll
            for (int mt = 0; mt < 2; ++mt) {
                const float* ap = A_s + (wm * 32 + mt * 16 + g) * AROW + k;
                a[mt][0] = __float_as_uint(ap[0]);
                a[mt][1] = __float_as_uint(ap[8 * AROW]);
                a[mt][2] = __float_as_uint(ap[4]);
                a[mt][3] = __float_as_uint(ap[8 * AROW + 4]);
            }
#pragma unroll
            for (int nt = 0; nt < 8; ++nt) {
                const float* bp = B_s + (wn * 64 + nt * 8 + g) * AROW + k;
                uint32_t b0 = __float_as_uint(bp[0]);
                uint32_t b1 = __float_as_uint(bp[4]);
                mma8(acc[0][nt], a[0], b0, b1);
                mma8(acc[1][nt], a[1], b0, b1);
            }
        }
        __syncthreads();
    }

    // epilogue: write accumulators straight to g_gates
#pragma unroll
    for (int mt = 0; mt < 2; ++mt) {
        const int r0 = m0 + wm * 32 + mt * 16 + g;
#pragma unroll
        for (int nt = 0; nt < 8; ++nt) {
            const int cc = n0 + wn * 64 + nt * 8 + 2 * tg;
            float2 v0 = make_float2(acc[mt][nt][0], acc[mt][nt][1]);
            float2 v1 = make_float2(acc[mt][nt][2], acc[mt][nt][3]);
            *(float2*)(g_gates + (size_t)r0 * G4H + cc) = v0;
            *(float2*)(g_gates + (size_t)(r0 + 8) * G4H + cc) = v1;
        }
    }
}

// ---------------- small prep kernels ----------------
__global__ void sum_blocks_kernel(const float* __restrict__ h_prev) {
    int b = blockIdx.x;
    int j = threadIdx.x;
    const float* hp = h_prev + (size_t)b * H_DIM + j;
    float acc = 0.f;
#pragma unroll
    for (int kb = 0; kb < KBLK; ++kb) acc += hp[kb * HB];
    g_s[b * HB + j] = acc;
}

__global__ void make_C_kernel(const float* __restrict__ A, const float* __restrict__ Bm) {
    int i = blockIdx.x * blockDim.x + threadIdx.x;
    g_C[i] = A[i] - Bm[i];
}

// ---------------- fp32 SIMT NT GEMM (small t matrix) ----------------
__global__ __launch_bounds__(256, 2)
void gemm_nt_kernel(const float* __restrict__ A, const float* __restrict__ B,
                    float* __restrict__ C,
                    int K, int lda, int ldb, int ldc) {
    __shared__ float As[16][128];
    __shared__ float Bs[16][128];

    const int m0 = blockIdx.y * 128;
    const int n0 = blockIdx.x * 128;
    const int tid = threadIdx.x;
    const int tx = tid & 15;
    const int ty = tid >> 4;

    float acc[8][8];
#pragma unroll
    for (int u = 0; u < 8; ++u)
#pragma unroll
        for (int v = 0; v < 8; ++v) acc[u][v] = 0.f;

    for (int k0 = 0; k0 < K; k0 += 16) {
#pragma unroll
        for (int l = 0; l < 2; ++l) {
            int f  = tid + l * 256;
            int r  = f >> 2;
            int c4 = (f & 3) * 4;
            float4 va = *(const float4*)(A + (size_t)(m0 + r) * lda + k0 + c4);
            As[c4 + 0][r] = va.x; As[c4 + 1][r] = va.y;
            As[c4 + 2][r] = va.z; As[c4 + 3][r] = va.w;
            float4 vb = *(const float4*)(B + (size_t)(n0 + r) * ldb + k0 + c4);
            Bs[c4 + 0][r] = vb.x; Bs[c4 + 1][r] = vb.y;
            Bs[c4 + 2][r] = vb.z; Bs[c4 + 3][r] = vb.w;
        }
        __syncthreads();
#pragma unroll
        for (int kk = 0; kk < 16; ++kk) {
            float a[8], b[8];
            *(float4*)&a[0] = *(const float4*)&As[kk][ty * 8];
            *(float4*)&a[4] = *(const float4*)&As[kk][ty * 8 + 4];
            *(float4*)&b[0] = *(const float4*)&Bs[kk][tx * 8];
            *(float4*)&b[4] = *(const float4*)&Bs[kk][tx * 8 + 4];
#pragma unroll
            for (int u = 0; u < 8; ++u)
#pragma unroll
                for (int v = 0; v < 8; ++v) acc[u][v] += a[u] * b[v];
        }
        __syncthreads();
    }

#pragma unroll
    for (int u = 0; u < 8; ++u) {
        float* crow = C + (size_t)(m0 + ty * 8 + u) * ldc + n0 + tx * 8;
#pragma unroll
        for (int v4 = 0; v4 < 2; ++v4) {
            float4 o;
            o.x = acc[u][v4 * 4 + 0]; o.y = acc[u][v4 * 4 + 1];
            o.z = acc[u][v4 * 4 + 2]; o.w = acc[u][v4 * 4 + 3];
            *(float4*)(crow + v4 * 4) = o;
        }
    }
}

// ---------------- structured block term (+= into gates) ----------------
__global__ __launch_bounds__(256, 2)
void struct_gemm_kernel(const float* __restrict__ h_prev) {
    const int g  = blockIdx.y;
    const float* A  = h_prev;
    const float* Bw = g_C + g * (HB * HB);

    __shared__ float As[16][128];
    __shared__ float Bs[16][128];

    const int m0 = blockIdx.x * 128;
    const int tid = threadIdx.x;
    const int tx = tid & 15;
    const int ty = tid >> 4;

    float acc[8][8];
#pragma unroll
    for (int u = 0; u < 8; ++u)
#pragma unroll
        for (int v = 0; v < 8; ++v) acc[u][v] = 0.f;

    for (int k0 = 0; k0 < 128; k0 += 16) {
#pragma unroll
        for (int l = 0; l < 2; ++l) {
            int f  = tid + l * 256;
            int r  = f >> 2;
            int c4 = (f & 3) * 4;
            float4 va = *(const float4*)(A + (size_t)(m0 + r) * 128 + k0 + c4);
            As[c4 + 0][r] = va.x; As[c4 + 1][r] = va.y;
            As[c4 + 2][r] = va.z; As[c4 + 3][r] = va.w;
            float4 vb = *(const float4*)(Bw + (size_t)r * 128 + k0 + c4);
            Bs[c4 + 0][r] = vb.x; Bs[c4 + 1][r] = vb.y;
            Bs[c4 + 2][r] = vb.z; Bs[c4 + 3][r] = vb.w;
        }
        __syncthreads();
#pragma unroll
        for (int kk = 0; kk < 16; ++kk) {
            float a[8], b[8];
            *(float4*)&a[0] = *(const float4*)&As[kk][ty * 8];
            *(float4*)&a[4] = *(const float4*)&As[kk][ty * 8 + 4];
            *(float4*)&b[0] = *(const float4*)&Bs[kk][tx * 8];
            *(float4*)&b[4] = *(const float4*)&Bs[kk][tx * 8 + 4];
#pragma unroll
            for (int u = 0; u < 8; ++u)
#pragma unroll
                for (int v = 0; v < 8; ++v) acc[u][v] += a[u] * b[v];
        }
        __syncthreads();
    }

#pragma unroll
    for (int u = 0; u < 8; ++u) {
        int m  = m0 + ty * 8 + u;
        int b  = m >> 4;
        int kb = m & 15;
        float* gp       = g_gates + (size_t)b * G4H + g * H_DIM + kb * HB + tx * 8;
        const float* tp = g_t + (size_t)b * (4 * HB) + g * HB + tx * 8;
#pragma unroll
        for (int v = 0; v < 8; ++v)
            gp[v] += acc[u][v] + tp[v];
    }
}

// ---------------- elementwise LSTM epilogue ----------------
__global__ void lstm_elem_kernel(const float* __restrict__ c_prev, float* __restrict__ out) {
    int t = blockIdx.x * blockDim.x + threadIdx.x;
    int b = t >> 11;
    int j = t & (H_DIM - 1);
    const float* Gp = g_gates + (size_t)b * G4H + j;
    float gi = Gp[0];
    float gf = Gp[H_DIM];
    float gg = Gp[2 * H_DIM];
    float go = Gp[3 * H_DIM];

    float i_ = 1.f / (1.f + expf(-gi));
    float f_ = 1.f / (1.f + expf(-gf));
    float g_ = tanhf(gg);
    float o_ = 1.f / (1.f + expf(-go));

    float c = f_ * c_prev[t] + i_ * g_;
    float h = o_ * tanhf(c);

    out[t] = h;
    out[B_SZ * H_DIM + t] = c;
}

// ---------------- launch ----------------
extern "C" void kernel_launch(void* const* d_in, const int* in_sizes, int n_in,
                              void* d_out, int out_size) {
    const float* x      = (const float*)d_in[0];
    const float* h_prev = (const float*)d_in[1];
    const float* c_prev = (const float*)d_in[2];
    const float* Win    = (const float*)d_in[3];
    const float* A      = (const float*)d_in[4];
    const float* Bm     = (const float*)d_in[5];
    float* out = (float*)d_out;

    void *p_s, *p_t, *p_x32, *p_w32;
    cudaGetSymbolAddress(&p_s, g_s);
    cudaGetSymbolAddress(&p_t, g_t);
    cudaGetSymbolAddress(&p_x32, g_x32);
    cudaGetSymbolAddress(&p_w32, g_w32);

    cudaFuncSetAttribute(gemm_mma_kernel, cudaFuncAttributeMaxDynamicSharedMemorySize,
                         GSMEM_BYTES);

    // 1) round operands to tf32 (kills truncation bias in the tensor path)
    conv_tf32_kernel<<<(B_SZ * IN_DIM / 4) / 256, 256>>>(x, (float*)p_x32);
    conv_tf32_kernel<<<(G4H * IN_DIM / 4) / 256, 256>>>(Win, (float*)p_w32);

    // 2) per-batch block sum + C = A - Bm
    sum_blocks_kernel<<<B_SZ, HB>>>(h_prev);
    make_C_kernel<<<64, 1024>>>(A, Bm);

    // 3) t = s @ Bm^T
    {
        dim3 grid(512 / 128, B_SZ / 128);
        gemm_nt_kernel<<<grid, 256>>>((const float*)p_s, Bm, (float*)p_t,
                                      HB, HB, HB, 4 * HB);
    }

    // 4) gates = x @ Win^T on tensor cores (mma.sync tf32)
    {
        dim3 grid(G4H / BN, B_SZ / BM);
        gemm_mma_kernel<<<grid, 256, GSMEM_BYTES>>>((const float*)p_x32, (const float*)p_w32);
    }

    // 5) gates += hp_blocks @ (A-Bm)^T + broadcast(t)
    {
        dim3 grid((B_SZ * KBLK) / 128, 4);
        struct_gemm_kernel<<<grid, 256>>>(h_prev);
    }

    // 6) elementwise LSTM cell
    lstm_elem_kernel<<<(B_SZ * H_DIM) / 256, 256>>>(c_prev, out);
}

// round 5
// speedup vs baseline: 2.7783x; 1.2320x over previous
#include <cuda_runtime.h>
#include <math.h>
#include <stdint.h>

#define B_SZ   1024
#define IN_DIM 2048
#define H_DIM  2048
#define KBLK   16
#define HB     128
#define G4H    8192   // 4*H

// ---------------- device scratch (no allocations allowed) ----------------
static __device__ float g_gates[B_SZ * G4H];       // 32 MB
static __device__ float g_s32[B_SZ * HB];          // 512 KB (tf32-rounded block sums)
static __device__ float g_C32[4 * HB * HB];        // 256 KB (tf32-rounded A - Bm)
static __device__ float g_Bm32[4 * HB * HB];       // 256 KB (tf32-rounded Bm)
static __device__ float g_x32[B_SZ * IN_DIM];      // 8 MB
static __device__ float g_h32[B_SZ * H_DIM];       // 8 MB
static __device__ float g_w32[G4H * IN_DIM];       // 64 MB

// ---------------- helpers ----------------
__device__ __forceinline__ uint32_t smem_u32(const void* p) {
    uint32_t a;
    asm("{ .reg .u64 t; cvta.to.shared.u64 t, %1; cvt.u32.u64 %0, t; }" : "=r"(a) : "l"(p));
    return a;
}
__device__ __forceinline__ void cp16(uint32_t dst, const void* src) {
    asm volatile("cp.async.cg.shared.global [%0], [%1], 16;" :: "r"(dst), "l"(src));
}
#define CP_COMMIT() asm volatile("cp.async.commit_group;" ::: "memory")

__device__ __forceinline__ void mma8(float* c, const uint32_t* a, uint32_t b0, uint32_t b1) {
    asm volatile(
        "mma.sync.aligned.m16n8k8.row.col.f32.tf32.tf32.f32 "
        "{%0,%1,%2,%3}, {%4,%5,%6,%7}, {%8,%9}, {%0,%1,%2,%3};"
        : "+f"(c[0]), "+f"(c[1]), "+f"(c[2]), "+f"(c[3])
        : "r"(a[0]), "r"(a[1]), "r"(a[2]), "r"(a[3]), "r"(b0), "r"(b1));
}
__device__ __forceinline__ float tf32r(float x) {
    uint32_t u;
    asm("cvt.rna.tf32.f32 %0, %1;" : "=r"(u) : "f"(x));
    return __uint_as_float(u);
}

// ---------------- tf32 rounding pre-pass ----------------
__global__ void conv_tf32_kernel(const float* __restrict__ in, float* __restrict__ out) {
    int i = blockIdx.x * blockDim.x + threadIdx.x;
    float4 v = ((const float4*)in)[i];
    float4 o;
    o.x = tf32r(v.x); o.y = tf32r(v.y); o.z = tf32r(v.z); o.w = tf32r(v.w);
    ((float4*)out)[i] = o;
}

// s32[b, j] = tf32( sum_kb h_prev[b, kb*128 + j] )
__global__ void sum_blocks_kernel(const float* __restrict__ h_prev) {
    int b = blockIdx.x;
    int j = threadIdx.x;
    const float* hp = h_prev + (size_t)b * H_DIM + j;
    float acc = 0.f;
#pragma unroll
    for (int kb = 0; kb < KBLK; ++kb) acc += hp[kb * HB];
    g_s32[b * HB + j] = tf32r(acc);
}

// C32 = tf32(A - Bm), Bm32 = tf32(Bm); 65536 elements as float4
__global__ void make_C_kernel(const float* __restrict__ A, const float* __restrict__ Bm) {
    int i = blockIdx.x * blockDim.x + threadIdx.x;
    float4 a = ((const float4*)A)[i];
    float4 b = ((const float4*)Bm)[i];
    float4 c, bb;
    c.x = tf32r(a.x - b.x); c.y = tf32r(a.y - b.y);
    c.z = tf32r(a.z - b.z); c.w = tf32r(a.w - b.w);
    bb.x = tf32r(b.x); bb.y = tf32r(b.y); bb.z = tf32r(b.z); bb.w = tf32r(b.w);
    ((float4*)g_C32)[i] = c;
    ((float4*)g_Bm32)[i] = bb;
}

// ---------------- fused tensor GEMM (K = 2048 + 128 + 128) ----------------
// gates[m, n0+i] = sum_k x32[m,k] w32[n0+i,k]            (main, K=2048)
//               + sum_j h32[m, kb*128+j] C32[g][i][j]    (struct, K=128)
//               + sum_j s32[m, j] Bm32[g][i][j]          (t term, K=128)
// CTA tile 128x128, BK=32, 3-stage cp.async, 1 sync/iter.
#define BM 128
#define BN 128
#define BKT 32
#define AROW 36
#define ASTG (BM * AROW)
#define BSTG (BN * AROW)
#define NSTG 3
#define NIT  72                    // 64 main + 4 struct + 4 t
#define GSMEM_BYTES (NSTG * (ASTG + BSTG) * 4)   // 110592

__global__ __launch_bounds__(256, 1)
void gemm_fused_kernel() {
    extern __shared__ float sm[];
    float* sA = sm;                      // [NSTG][BM][AROW]
    float* sB = sm + NSTG * ASTG;        // [NSTG][BN][AROW]

    const int tid  = threadIdx.x;
    const int m0   = blockIdx.y * BM;
    const int n0   = blockIdx.x * BN;
    const int gI   = n0 >> 11;            // gate index 0..3
    const int kb   = (n0 >> 7) & 15;      // block index 0..15
    const int wid  = tid >> 5, lane = tid & 31;
    const int g    = lane >> 2, tg = lane & 3;
    const int wm   = wid & 3;
    const int wn   = wid >> 2;

    float acc[2][8][4];
#pragma unroll
    for (int mt = 0; mt < 2; ++mt)
#pragma unroll
        for (int nt = 0; nt < 8; ++nt)
#pragma unroll
            for (int q = 0; q < 4; ++q) acc[mt][nt][q] = 0.f;

    const uint32_t sAa = smem_u32(sA);
    const uint32_t sBa = smem_u32(sB);
    const int lrow = tid >> 3;            // 0..31 base row step (x4 over j)
    const int lkc  = (tid & 7) * 4;       // k-offset in floats {0,4,...,28}

    auto load = [&](int it) {
        const int s = it % NSTG;
        const float* ab; int alda;
        const float* bb; int blda;
        if (it < 64) {
            ab = g_x32 + (size_t)m0 * IN_DIM + it * BKT;        alda = IN_DIM;
            bb = g_w32 + (size_t)n0 * IN_DIM + it * BKT;        blda = IN_DIM;
        } else if (it < 68) {
            ab = g_h32 + (size_t)m0 * H_DIM + kb * HB + (it - 64) * BKT;  alda = H_DIM;
            bb = g_C32 + gI * (HB * HB) + (it - 64) * BKT;                blda = HB;
        } else {
            ab = g_s32 + (size_t)m0 * HB + (it - 68) * BKT;     alda = HB;
            bb = g_Bm32 + gI * (HB * HB) + (it - 68) * BKT;     blda = HB;
        }
#pragma unroll
        for (int j = 0; j < 4; ++j) {
            int row = lrow + j * 32;
            cp16(sAa + (s * ASTG + row * AROW + lkc) * 4, ab + (size_t)row * alda + lkc);
        }
#pragma unroll
        for (int j = 0; j < 4; ++j) {
            int row = lrow + j * 32;
            cp16(sBa + (s * BSTG + row * AROW + lkc) * 4, bb + (size_t)row * blda + lkc);
        }
        CP_COMMIT();
    };

    load(0); load(1);

    for (int it = 0; it < NIT; ++it) {
        if (it < NIT - 1) asm volatile("cp.async.wait_group 1;" ::: "memory");
        else              asm volatile("cp.async.wait_group 0;" ::: "memory");
        __syncthreads();
        if (it + 2 < NIT) load(it + 2);

        const float* A_s = sA + (it % NSTG) * ASTG;
        const float* B_s = sB + (it % NSTG) * BSTG;

#pragma unroll
        for (int ks = 0; ks < 4; ++ks) {
            const int k = ks * 8 + tg;
            uint32_t a[2][4];
#pragma unroll
            for (int mt = 0; mt < 2; ++mt) {
                const float* ap = A_s + (wm * 32 + mt * 16 + g) * AROW + k;
                a[mt][0] = __float_as_uint(ap[0]);
                a[mt][1] = __float_as_uint(ap[8 * AROW]);
                a[mt][2] = __float_as_uint(ap[4]);
                a[mt][3] = __float_as_uint(ap[8 * AROW + 4]);
            }
#pragma unroll
            for (int nt = 0; nt < 8; ++nt) {
                const float* bp = B_s + (wn * 64 + nt * 8 + g) * AROW + k;
                uint32_t b0 = __float_as_uint(bp[0]);
                uint32_t b1 = __float_as_uint(bp[4]);
                mma8(acc[0][nt], a[0], b0, b1);
                mma8(acc[1][nt], a[1], b0, b1);
            }
        }
    }

    // epilogue: write final gates
#pragma unroll
    for (int mt = 0; mt < 2; ++mt) {
        const int r0 = m0 + wm * 32 + mt * 16 + g;
#pragma unroll
        for (int nt = 0; nt < 8; ++nt) {
            const int cc = n0 + wn * 64 + nt * 8 + 2 * tg;
            float2 v0 = make_float2(acc[mt][nt][0], acc[mt][nt][1]);
            float2 v1 = make_float2(acc[mt][nt][2], acc[mt][nt][3]);
            *(float2*)(g_gates + (size_t)r0 * G4H + cc) = v0;
            *(float2*)(g_gates + (size_t)(r0 + 8) * G4H + cc) = v1;
        }
    }
}

// ---------------- elementwise LSTM epilogue ----------------
__global__ void lstm_elem_kernel(const float* __restrict__ c_prev, float* __restrict__ out) {
    int t = blockIdx.x * blockDim.x + threadIdx.x;
    int b = t >> 11;
    int j = t & (H_DIM - 1);
    const float* Gp = g_gates + (size_t)b * G4H + j;
    float gi = Gp[0];
    float gf = Gp[H_DIM];
    float gg = Gp[2 * H_DIM];
    float go = Gp[3 * H_DIM];

    float i_ = 1.f / (1.f + expf(-gi));
    float f_ = 1.f / (1.f + expf(-gf));
    float g_ = tanhf(gg);
    float o_ = 1.f / (1.f + expf(-go));

    float c = f_ * c_prev[t] + i_ * g_;
    float h = o_ * tanhf(c);

    out[t] = h;
    out[B_SZ * H_DIM + t] = c;
}

// ---------------- launch ----------------
extern "C" void kernel_launch(void* const* d_in, const int* in_sizes, int n_in,
                              void* d_out, int out_size) {
    const float* x      = (const float*)d_in[0];
    const float* h_prev = (const float*)d_in[1];
    const float* c_prev = (const float*)d_in[2];
    const float* Win    = (const float*)d_in[3];
    const float* A      = (const float*)d_in[4];
    const float* Bm     = (const float*)d_in[5];
    float* out = (float*)d_out;

    void *p_x32, *p_h32, *p_w32;
    cudaGetSymbolAddress(&p_x32, g_x32);
    cudaGetSymbolAddress(&p_h32, g_h32);
    cudaGetSymbolAddress(&p_w32, g_w32);

    cudaFuncSetAttribute(gemm_fused_kernel, cudaFuncAttributeMaxDynamicSharedMemorySize,
                         GSMEM_BYTES);

    // 1) tf32-round all GEMM operands
    conv_tf32_kernel<<<(B_SZ * IN_DIM / 4) / 256, 256>>>(x, (float*)p_x32);
    conv_tf32_kernel<<<(B_SZ * H_DIM / 4) / 256, 256>>>(h_prev, (float*)p_h32);
    conv_tf32_kernel<<<(G4H * IN_DIM / 4) / 256, 256>>>(Win, (float*)p_w32);
    sum_blocks_kernel<<<B_SZ, HB>>>(h_prev);
    make_C_kernel<<<64, 256>>>(A, Bm);

    // 2) fused gates GEMM (main + struct + t) on tensor cores
    {
        dim3 grid(G4H / BN, B_SZ / BM);
        gemm_fused_kernel<<<grid, 256, GSMEM_BYTES>>>();
    }

    // 3) elementwise LSTM cell
    lstm_elem_kernel<<<(B_SZ * H_DIM) / 256, 256>>>(c_prev, out);
}

// round 7
// speedup vs baseline: 3.2460x; 1.1683x over previous
#include <cuda_runtime.h>
#include <math.h>
#include <stdint.h>

#define B_SZ   1024
#define IN_DIM 2048
#define H_DIM  2048
#define KBLK   16
#define HB     128
#define G4H    8192   // 4*H

// ---------------- device scratch (no allocations allowed) ----------------
static __device__ float g_gates[B_SZ * G4H];       // 32 MB
static __device__ float g_s[B_SZ * HB];            // 512 KB (fp32 block sums)
static __device__ float g_t[B_SZ * 4 * HB];        // 2 MB (fp32 t = s @ Bm^T)
static __device__ float g_C32[4 * HB * HB];        // 256 KB (tf32-rounded A - Bm)
static __device__ float g_x32[B_SZ * IN_DIM];      // 8 MB
static __device__ float g_h32[B_SZ * H_DIM];       // 8 MB
static __device__ float g_w32[G4H * IN_DIM];       // 64 MB

// ---------------- helpers ----------------
__device__ __forceinline__ uint32_t smem_u32(const void* p) {
    uint32_t a;
    asm("{ .reg .u64 t; cvta.to.shared.u64 t, %1; cvt.u32.u64 %0, t; }" : "=r"(a) : "l"(p));
    return a;
}
__device__ __forceinline__ void cp16(uint32_t dst, const void* src) {
    asm volatile("cp.async.cg.shared.global [%0], [%1], 16;" :: "r"(dst), "l"(src));
}
#define CP_COMMIT() asm volatile("cp.async.commit_group;" ::: "memory")

__device__ __forceinline__ void mma8(float* c, const uint32_t* a, uint32_t b0, uint32_t b1) {
    asm volatile(
        "mma.sync.aligned.m16n8k8.row.col.f32.tf32.tf32.f32 "
        "{%0,%1,%2,%3}, {%4,%5,%6,%7}, {%8,%9}, {%0,%1,%2,%3};"
        : "+f"(c[0]), "+f"(c[1]), "+f"(c[2]), "+f"(c[3])
        : "r"(a[0]), "r"(a[1]), "r"(a[2]), "r"(a[3]), "r"(b0), "r"(b1));
}
__device__ __forceinline__ float tf32r(float x) {
    uint32_t u;
    asm("cvt.rna.tf32.f32 %0, %1;" : "=r"(u) : "f"(x));
    return __uint_as_float(u);
}

// ---------------- tf32 rounding pre-pass ----------------
__global__ void conv_tf32_kernel(const float* __restrict__ in, float* __restrict__ out) {
    int i = blockIdx.x * blockDim.x + threadIdx.x;
    float4 v = ((const float4*)in)[i];
    float4 o;
    o.x = tf32r(v.x); o.y = tf32r(v.y); o.z = tf32r(v.z); o.w = tf32r(v.w);
    ((float4*)out)[i] = o;
}

// s[b, j] = sum_kb h_prev[b, kb*128 + j]  (fp32, no rounding)
__global__ void sum_blocks_kernel(const float* __restrict__ h_prev) {
    int b = blockIdx.x;
    int j = threadIdx.x;
    const float* hp = h_prev + (size_t)b * H_DIM + j;
    float acc = 0.f;
#pragma unroll
    for (int kb = 0; kb < KBLK; ++kb) acc += hp[kb * HB];
    g_s[b * HB + j] = acc;
}

// C32 = tf32(A - Bm)
__global__ void make_C_kernel(const float* __restrict__ A, const float* __restrict__ Bm) {
    int i = blockIdx.x * blockDim.x + threadIdx.x;
    float4 a = ((const float4*)A)[i];
    float4 b = ((const float4*)Bm)[i];
    float4 c;
    c.x = tf32r(a.x - b.x); c.y = tf32r(a.y - b.y);
    c.z = tf32r(a.z - b.z); c.w = tf32r(a.w - b.w);
    ((float4*)g_C32)[i] = c;
}

// ---------------- fused tensor GEMM (K = 2048 + 128) ----------------
// gates[m, n0+i] = sum_k x32[m,k] w32[n0+i,k] + sum_j h32[m, kb*128+j] C32[g][i][j]
// CTA tile 256x128, BK=32, 3-stage cp.async. 8 warps = 4(m) x 2(n), warp 64x64.
#define BM 256
#define BN 128
#define BKT 32
#define AROW 36
#define ASTG (BM * AROW)          // 9216 floats
#define BSTG (BN * AROW)          // 4608 floats
#define NSTG 3
#define NIT  68                   // 64 main + 4 struct
#define GSMEM_BYTES (NSTG * (ASTG + BSTG) * 4)   // 165888

__global__ __launch_bounds__(256, 1)
void gemm_fused_kernel() {
    extern __shared__ float sm[];
    float* sA = sm;                      // [NSTG][BM][AROW]
    float* sB = sm + NSTG * ASTG;        // [NSTG][BN][AROW]

    const int tid  = threadIdx.x;
    const int m0   = blockIdx.y * BM;
    const int n0   = blockIdx.x * BN;
    const int gI   = n0 >> 11;            // gate 0..3
    const int kb   = (n0 >> 7) & 15;      // block 0..15
    const int wid  = tid >> 5, lane = tid & 31;
    const int g    = lane >> 2, tg = lane & 3;
    const int wm   = wid & 3;             // 4 m-positions (64 rows each)
    const int wn   = wid >> 2;            // 2 n-positions (64 cols each)

    float acc[4][8][4];
#pragma unroll
    for (int mt = 0; mt < 4; ++mt)
#pragma unroll
        for (int nt = 0; nt < 8; ++nt)
#pragma unroll
            for (int q = 0; q < 4; ++q) acc[mt][nt][q] = 0.f;

    const uint32_t sAa = smem_u32(sA);
    const uint32_t sBa = smem_u32(sB);
    const int lrow = tid >> 3;            // 0..31
    const int lkc  = (tid & 7) * 4;       // {0,4,...,28}

    auto load = [&](int it) {
        const int s = it % NSTG;
        const float* ab; int alda;
        const float* bb; int blda;
        if (it < 64) {
            ab = g_x32 + (size_t)m0 * IN_DIM + it * BKT;   alda = IN_DIM;
            bb = g_w32 + (size_t)n0 * IN_DIM + it * BKT;   blda = IN_DIM;
        } else {
            ab = g_h32 + (size_t)m0 * H_DIM + kb * HB + (it - 64) * BKT;  alda = H_DIM;
            bb = g_C32 + gI * (HB * HB) + (it - 64) * BKT;                blda = HB;
        }
#pragma unroll
        for (int j = 0; j < 8; ++j) {      // A: 256 rows
            int row = lrow + j * 32;
            cp16(sAa + (s * ASTG + row * AROW + lkc) * 4, ab + (size_t)row * alda + lkc);
        }
#pragma unroll
        for (int j = 0; j < 4; ++j) {      // B: 128 rows
            int row = lrow + j * 32;
            cp16(sBa + (s * BSTG + row * AROW + lkc) * 4, bb + (size_t)row * blda + lkc);
        }
        CP_COMMIT();
    };

    load(0); load(1);

    for (int it = 0; it < NIT; ++it) {
        if (it < NIT - 1) asm volatile("cp.async.wait_group 1;" ::: "memory");
        else              asm volatile("cp.async.wait_group 0;" ::: "memory");
        __syncthreads();
        if (it + 2 < NIT) load(it + 2);

        const float* A_s = sA + (it % NSTG) * ASTG;
        const float* B_s = sB + (it % NSTG) * BSTG;

#pragma unroll
        for (int ks = 0; ks < 4; ++ks) {
            const int k = ks * 8 + tg;
            uint32_t a[4][4];
#pragma unroll
            for (int mt = 0; mt < 4; ++mt) {
                const float* ap = A_s + (wm * 64 + mt * 16 + g) * AROW + k;
                a[mt][0] = __float_as_uint(ap[0]);
                a[mt][1] = __float_as_uint(ap[8 * AROW]);
                a[mt][2] = __float_as_uint(ap[4]);
                a[mt][3] = __float_as_uint(ap[8 * AROW + 4]);
            }
            uint32_t bf[8][2];
#pragma unroll
            for (int nt = 0; nt < 8; ++nt) {
                const float* bp = B_s + (wn * 64 + nt * 8 + g) * AROW + k;
                bf[nt][0] = __float_as_uint(bp[0]);
                bf[nt][1] = __float_as_uint(bp[4]);
            }
#pragma unroll
            for (int nt = 0; nt < 8; ++nt)
#pragma unroll
                for (int mt = 0; mt < 4; ++mt)
                    mma8(acc[mt][nt], a[mt], bf[nt][0], bf[nt][1]);
        }
    }

    // epilogue
#pragma unroll
    for (int mt = 0; mt < 4; ++mt) {
        const int r0 = m0 + wm * 64 + mt * 16 + g;
#pragma unroll
        for (int nt = 0; nt < 8; ++nt) {
            const int cc = n0 + wn * 64 + nt * 8 + 2 * tg;
            float2 v0 = make_float2(acc[mt][nt][0], acc[mt][nt][1]);
            float2 v1 = make_float2(acc[mt][nt][2], acc[mt][nt][3]);
            *(float2*)(g_gates + (size_t)r0 * G4H + cc) = v0;
            *(float2*)(g_gates + (size_t)(r0 + 8) * G4H + cc) = v1;
        }
    }
}

// ---------------- fp32 SIMT NT GEMM for t = s @ Bm^T ----------------
__global__ __launch_bounds__(256, 2)
void gemm_nt_kernel(const float* __restrict__ A, const float* __restrict__ B,
                    float* __restrict__ C,
                    int K, int lda, int ldb, int ldc) {
    __shared__ float As[16][128];
    __shared__ float Bs[16][128];

    const int m0 = blockIdx.y * 128;
    const int n0 = blockIdx.x * 128;
    const int tid = threadIdx.x;
    const int tx = tid & 15;
    const int ty = tid >> 4;

    float acc[8][8];
#pragma unroll
    for (int u = 0; u < 8; ++u)
#pragma unroll
        for (int v = 0; v < 8; ++v) acc[u][v] = 0.f;

    for (int k0 = 0; k0 < K; k0 += 16) {
#pragma unroll
        for (int l = 0; l < 2; ++l) {
            int f  = tid + l * 256;
            int r  = f >> 2;
            int c4 = (f & 3) * 4;
            float4 va = *(const float4*)(A + (size_t)(m0 + r) * lda + k0 + c4);
            As[c4 + 0][r] = va.x; As[c4 + 1][r] = va.y;
            As[c4 + 2][r] = va.z; As[c4 + 3][r] = va.w;
            float4 vb = *(const float4*)(B + (size_t)(n0 + r) * ldb + k0 + c4);
            Bs[c4 + 0][r] = vb.x; Bs[c4 + 1][r] = vb.y;
            Bs[c4 + 2][r] = vb.z; Bs[c4 + 3][r] = vb.w;
        }
        __syncthreads();
#pragma unroll
        for (int kk = 0; kk < 16; ++kk) {
            float a[8], b[8];
            *(float4*)&a[0] = *(const float4*)&As[kk][ty * 8];
            *(float4*)&a[4] = *(const float4*)&As[kk][ty * 8 + 4];
            *(float4*)&b[0] = *(const float4*)&Bs[kk][tx * 8];
            *(float4*)&b[4] = *(const float4*)&Bs[kk][tx * 8 + 4];
#pragma unroll
            for (int u = 0; u < 8; ++u)
#pragma unroll
                for (int v = 0; v < 8; ++v) acc[u][v] += a[u] * b[v];
        }
        __syncthreads();
    }

#pragma unroll
    for (int u = 0; u < 8; ++u) {
        float* crow = C + (size_t)(m0 + ty * 8 + u) * ldc + n0 + tx * 8;
#pragma unroll
        for (int v4 = 0; v4 < 2; ++v4) {
            float4 o;
            o.x = acc[u][v4 * 4 + 0]; o.y = acc[u][v4 * 4 + 1];
            o.z = acc[u][v4 * 4 + 2]; o.w = acc[u][v4 * 4 + 3];
            *(float4*)(crow + v4 * 4) = o;
        }
    }
}

// ---------------- elementwise LSTM epilogue (adds fp32 t-term) ----------------
__global__ void lstm_elem_kernel(const float* __restrict__ c_prev, float* __restrict__ out) {
    int t = blockIdx.x * blockDim.x + threadIdx.x;
    int b = t >> 11;
    int j = t & (H_DIM - 1);
    int jj = j & (HB - 1);
    const float* Gp = g_gates + (size_t)b * G4H + j;
    const float* tp = g_t + (size_t)b * (4 * HB) + jj;
    float gi = Gp[0]          + tp[0];
    float gf = Gp[H_DIM]      + tp[HB];
    float gg = Gp[2 * H_DIM]  + tp[2 * HB];
    float go = Gp[3 * H_DIM]  + tp[3 * HB];

    float i_ = 1.f / (1.f + expf(-gi));
    float f_ = 1.f / (1.f + expf(-gf));
    float g_ = tanhf(gg);
    float o_ = 1.f / (1.f + expf(-go));

    float c = f_ * c_prev[t] + i_ * g_;
    float h = o_ * tanhf(c);

    out[t] = h;
    out[B_SZ * H_DIM + t] = c;
}

// ---------------- launch ----------------
extern "C" void kernel_launch(void* const* d_in, const int* in_sizes, int n_in,
                              void* d_out, int out_size) {
    const float* x      = (const float*)d_in[0];
    const float* h_prev = (const float*)d_in[1];
    const float* c_prev = (const float*)d_in[2];
    const float* Win    = (const float*)d_in[3];
    const float* A      = (const float*)d_in[4];
    const float* Bm     = (const float*)d_in[5];
    float* out = (float*)d_out;

    void *p_x32, *p_h32, *p_w32, *p_s, *p_t;
    cudaGetSymbolAddress(&p_x32, g_x32);
    cudaGetSymbolAddress(&p_h32, g_h32);
    cudaGetSymbolAddress(&p_w32, g_w32);
    cudaGetSymbolAddress(&p_s, g_s);
    cudaGetSymbolAddress(&p_t, g_t);

    cudaFuncSetAttribute(gemm_fused_kernel, cudaFuncAttributeMaxDynamicSharedMemorySize,
                         GSMEM_BYTES);

    // 1) tf32-round GEMM operands; fp32 block sums
    conv_tf32_kernel<<<(B_SZ * IN_DIM / 4) / 256, 256>>>(x, (float*)p_x32);
    conv_tf32_kernel<<<(B_SZ * H_DIM / 4) / 256, 256>>>(h_prev, (float*)p_h32);
    conv_tf32_kernel<<<(G4H * IN_DIM / 4) / 256, 256>>>(Win, (float*)p_w32);
    sum_blocks_kernel<<<B_SZ, HB>>>(h_prev);
    make_C_kernel<<<64, 256>>>(A, Bm);

    // 2) fp32 t = s @ Bm^T  ([1024,128] x [512,128]^T -> [1024,512])
    {
        dim3 grid(512 / 128, B_SZ / 128);
        gemm_nt_kernel<<<grid, 256>>>((const float*)p_s, Bm, (float*)p_t,
                                      HB, HB, HB, 4 * HB);
    }

    // 3) fused gates GEMM (main + struct) on tensor cores
    {
        dim3 grid(G4H / BN, B_SZ / BM);
        gemm_fused_kernel<<<grid, 256, GSMEM_BYTES>>>();
    }

    // 4) elementwise LSTM cell (+ t-term)
    lstm_elem_kernel<<<(B_SZ * H_DIM) / 256, 256>>>(c_prev, out);
}

// round 9
// speedup vs baseline: 3.5228x; 1.0853x over previous
#include <cuda_runtime.h>
#include <math.h>
#include <stdint.h>

#define B_SZ   1024
#define IN_DIM 2048
#define H_DIM  2048
#define KBLK   16
#define HB     128
#define G4H    8192   // 4*H

// ---------------- device scratch (no allocations allowed) ----------------
static __device__ float g_gates[B_SZ * G4H];       // 32 MB
static __device__ float g_s[B_SZ * HB];            // 512 KB (fp32 block sums)
static __device__ float g_t[B_SZ * 4 * HB];        // 2 MB (fp32 t = s @ Bm^T)
static __device__ float g_C32[4 * HB * HB];        // 256 KB (tf32-rounded A - Bm)
static __device__ float g_x32[B_SZ * IN_DIM];      // 8 MB
static __device__ float g_h32[B_SZ * H_DIM];       // 8 MB

// ---------------- helpers ----------------
__device__ __forceinline__ uint32_t smem_u32(const void* p) {
    uint32_t a;
    asm("{ .reg .u64 t; cvta.to.shared.u64 t, %1; cvt.u32.u64 %0, t; }" : "=r"(a) : "l"(p));
    return a;
}
__device__ __forceinline__ void cp16(uint32_t dst, const void* src) {
    asm volatile("cp.async.cg.shared.global [%0], [%1], 16;" :: "r"(dst), "l"(src));
}
#define CP_COMMIT() asm volatile("cp.async.commit_group;" ::: "memory")

__device__ __forceinline__ void mma8(float* c, const uint32_t* a, uint32_t b0, uint32_t b1) {
    asm volatile(
        "mma.sync.aligned.m16n8k8.row.col.f32.tf32.tf32.f32 "
        "{%0,%1,%2,%3}, {%4,%5,%6,%7}, {%8,%9}, {%0,%1,%2,%3};"
        : "+f"(c[0]), "+f"(c[1]), "+f"(c[2]), "+f"(c[3])
        : "r"(a[0]), "r"(a[1]), "r"(a[2]), "r"(a[3]), "r"(b0), "r"(b1));
}
__device__ __forceinline__ float tf32r(float x) {
    uint32_t u;
    asm("cvt.rna.tf32.f32 %0, %1;" : "=r"(u) : "f"(x));
    return __uint_as_float(u);
}

// ---------------- tf32 rounding pre-pass (x, h only) ----------------
__global__ void conv_tf32_kernel(const float* __restrict__ in, float* __restrict__ out) {
    int i = blockIdx.x * blockDim.x + threadIdx.x;
    float4 v = ((const float4*)in)[i];
    float4 o;
    o.x = tf32r(v.x); o.y = tf32r(v.y); o.z = tf32r(v.z); o.w = tf32r(v.w);
    ((float4*)out)[i] = o;
}

// s[b, j] = sum_kb h_prev[b, kb*128 + j]  (fp32)
__global__ void sum_blocks_kernel(const float* __restrict__ h_prev) {
    int b = blockIdx.x;
    int j = threadIdx.x;
    const float* hp = h_prev + (size_t)b * H_DIM + j;
    float acc = 0.f;
#pragma unroll
    for (int kb = 0; kb < KBLK; ++kb) acc += hp[kb * HB];
    g_s[b * HB + j] = acc;
}

// C32 = tf32(A - Bm)
__global__ void make_C_kernel(const float* __restrict__ A, const float* __restrict__ Bm) {
    int i = blockIdx.x * blockDim.x + threadIdx.x;
    float4 a = ((const float4*)A)[i];
    float4 b = ((const float4*)Bm)[i];
    float4 c;
    c.x = tf32r(a.x - b.x); c.y = tf32r(a.y - b.y);
    c.z = tf32r(a.z - b.z); c.w = tf32r(a.w - b.w);
    ((float4*)g_C32)[i] = c;
}

// ---------------- fused tensor GEMM (K = 2048 + 128) ----------------
// gates[m, n0+i] = sum_k x32[m,k] Win[n0+i,k] + sum_j h32[m, kb*128+j] C32[g][i][j]
// W is consumed raw (in-instruction tf32 truncation on B operand only).
// CTA tile 256x128, BK=32, 3-stage cp.async. 8 warps = 4(m) x 2(n), warp 64x64.
#define BM 256
#define BN 128
#define BKT 32
#define AROW 36
#define ASTG (BM * AROW)          // 9216 floats
#define BSTG (BN * AROW)          // 4608 floats
#define NSTG 3
#define NIT  68                   // 64 main + 4 struct
#define GSMEM_BYTES (NSTG * (ASTG + BSTG) * 4)   // 165888

__global__ __launch_bounds__(256, 1)
void gemm_fused_kernel(const float* __restrict__ W) {
    extern __shared__ float sm[];
    float* sA = sm;                      // [NSTG][BM][AROW]
    float* sB = sm + NSTG * ASTG;        // [NSTG][BN][AROW]

    const int tid  = threadIdx.x;
    const int m0   = blockIdx.y * BM;
    const int n0   = blockIdx.x * BN;
    const int gI   = n0 >> 11;            // gate 0..3
    const int kb   = (n0 >> 7) & 15;      // block 0..15
    const int wid  = tid >> 5, lane = tid & 31;
    const int g    = lane >> 2, tg = lane & 3;
    const int wm   = wid & 3;             // 4 m-positions (64 rows each)
    const int wn   = wid >> 2;            // 2 n-positions (64 cols each)

    float acc[4][8][4];
#pragma unroll
    for (int mt = 0; mt < 4; ++mt)
#pragma unroll
        for (int nt = 0; nt < 8; ++nt)
#pragma unroll
            for (int q = 0; q < 4; ++q) acc[mt][nt][q] = 0.f;

    const uint32_t sAa = smem_u32(sA);
    const uint32_t sBa = smem_u32(sB);
    const int lrow = tid >> 3;            // 0..31
    const int lkc  = (tid & 7) * 4;       // {0,4,...,28}

    auto load = [&](int it) {
        const int s = it % NSTG;
        const float* ab; int alda;
        const float* bb; int blda;
        if (it < 64) {
            ab = g_x32 + (size_t)m0 * IN_DIM + it * BKT;   alda = IN_DIM;
            bb = W + (size_t)n0 * IN_DIM + it * BKT;       blda = IN_DIM;
        } else {
            ab = g_h32 + (size_t)m0 * H_DIM + kb * HB + (it - 64) * BKT;  alda = H_DIM;
            bb = g_C32 + gI * (HB * HB) + (it - 64) * BKT;                blda = HB;
        }
#pragma unroll
        for (int j = 0; j < 8; ++j) {      // A: 256 rows
            int row = lrow + j * 32;
            cp16(sAa + (s * ASTG + row * AROW + lkc) * 4, ab + (size_t)row * alda + lkc);
        }
#pragma unroll
        for (int j = 0; j < 4; ++j) {      // B: 128 rows
            int row = lrow + j * 32;
            cp16(sBa + (s * BSTG + row * AROW + lkc) * 4, bb + (size_t)row * blda + lkc);
        }
        CP_COMMIT();
    };

    load(0); load(1);

    for (int it = 0; it < NIT; ++it) {
        if (it < NIT - 1) asm volatile("cp.async.wait_group 1;" ::: "memory");
        else              asm volatile("cp.async.wait_group 0;" ::: "memory");
        __syncthreads();
        if (it + 2 < NIT) load(it + 2);

        const float* A_s = sA + (it % NSTG) * ASTG;
        const float* B_s = sB + (it % NSTG) * BSTG;

#pragma unroll
        for (int ks = 0; ks < 4; ++ks) {
            const int k = ks * 8 + tg;
            uint32_t a[4][4];
#pragma unroll
            for (int mt = 0; mt < 4; ++mt) {
                const float* ap = A_s + (wm * 64 + mt * 16 + g) * AROW + k;
                a[mt][0] = __float_as_uint(ap[0]);
                a[mt][1] = __float_as_uint(ap[8 * AROW]);
                a[mt][2] = __float_as_uint(ap[4]);
                a[mt][3] = __float_as_uint(ap[8 * AROW + 4]);
            }
            uint32_t bf[8][2];
#pragma unroll
            for (int nt = 0; nt < 8; ++nt) {
                const float* bp = B_s + (wn * 64 + nt * 8 + g) * AROW + k;
                bf[nt][0] = __float_as_uint(bp[0]);
                bf[nt][1] = __float_as_uint(bp[4]);
            }
#pragma unroll
            for (int nt = 0; nt < 8; ++nt)
#pragma unroll
                for (int mt = 0; mt < 4; ++mt)
                    mma8(acc[mt][nt], a[mt], bf[nt][0], bf[nt][1]);
        }
    }

    // epilogue
#pragma unroll
    for (int mt = 0; mt < 4; ++mt) {
        const int r0 = m0 + wm * 64 + mt * 16 + g;
#pragma unroll
        for (int nt = 0; nt < 8; ++nt) {
            const int cc = n0 + wn * 64 + nt * 8 + 2 * tg;
            float2 v0 = make_float2(acc[mt][nt][0], acc[mt][nt][1]);
            float2 v1 = make_float2(acc[mt][nt][2], acc[mt][nt][3]);
            *(float2*)(g_gates + (size_t)r0 * G4H + cc) = v0;
            *(float2*)(g_gates + (size_t)(r0 + 8) * G4H + cc) = v1;
        }
    }
}

// ---------------- fp32 SIMT NT GEMM for t = s @ Bm^T ----------------
__global__ __launch_bounds__(256, 2)
void gemm_nt_kernel(const float* __restrict__ A, const float* __restrict__ B,
                    float* __restrict__ C,
                    int K, int lda, int ldb, int ldc) {
    __shared__ float As[16][128];
    __shared__ float Bs[16][128];

    const int m0 = blockIdx.y * 128;
    const int n0 = blockIdx.x * 128;
    const int tid = threadIdx.x;
    const int tx = tid & 15;
    const int ty = tid >> 4;

    float acc[8][8];
#pragma unroll
    for (int u = 0; u < 8; ++u)
#pragma unroll
        for (int v = 0; v < 8; ++v) acc[u][v] = 0.f;

    for (int k0 = 0; k0 < K; k0 += 16) {
#pragma unroll
        for (int l = 0; l < 2; ++l) {
            int f  = tid + l * 256;
            int r  = f >> 2;
            int c4 = (f & 3) * 4;
            float4 va = *(const float4*)(A + (size_t)(m0 + r) * lda + k0 + c4);
            As[c4 + 0][r] = va.x; As[c4 + 1][r] = va.y;
            As[c4 + 2][r] = va.z; As[c4 + 3][r] = va.w;
            float4 vb = *(const float4*)(B + (size_t)(n0 + r) * ldb + k0 + c4);
            Bs[c4 + 0][r] = vb.x; Bs[c4 + 1][r] = vb.y;
            Bs[c4 + 2][r] = vb.z; Bs[c4 + 3][r] = vb.w;
        }
        __syncthreads();
#pragma unroll
        for (int kk = 0; kk < 16; ++kk) {
            float a[8], b[8];
            *(float4*)&a[0] = *(const float4*)&As[kk][ty * 8];
            *(float4*)&a[4] = *(const float4*)&As[kk][ty * 8 + 4];
            *(float4*)&b[0] = *(const float4*)&Bs[kk][tx * 8];
            *(float4*)&b[4] = *(const float4*)&Bs[kk][tx * 8 + 4];
#pragma unroll
            for (int u = 0; u < 8; ++u)
#pragma unroll
                for (int v = 0; v < 8; ++v) acc[u][v] += a[u] * b[v];
        }
        __syncthreads();
    }

#pragma unroll
    for (int u = 0; u < 8; ++u) {
        float* crow = C + (size_t)(m0 + ty * 8 + u) * ldc + n0 + tx * 8;
#pragma unroll
        for (int v4 = 0; v4 < 2; ++v4) {
            float4 o;
            o.x = acc[u][v4 * 4 + 0]; o.y = acc[u][v4 * 4 + 1];
            o.z = acc[u][v4 * 4 + 2]; o.w = acc[u][v4 * 4 + 3];
            *(float4*)(crow + v4 * 4) = o;
        }
    }
}

// ---------------- elementwise LSTM epilogue (float4, adds fp32 t-term) ----------------
__global__ void lstm_elem_kernel(const float* __restrict__ c_prev, float* __restrict__ out) {
    int t = blockIdx.x * blockDim.x + threadIdx.x;   // 0 .. B*H/4-1
    int b = t >> 9;                     // 512 float4 per batch row
    int j = (t & 511) * 4;
    int jj = j & (HB - 1);
    const float* Gp = g_gates + (size_t)b * G4H + j;
    const float* tp = g_t + (size_t)b * (4 * HB) + jj;

    float4 gi = *(const float4*)(Gp);
    float4 gf = *(const float4*)(Gp + H_DIM);
    float4 gg = *(const float4*)(Gp + 2 * H_DIM);
    float4 go = *(const float4*)(Gp + 3 * H_DIM);
    float4 ti = *(const float4*)(tp);
    float4 tf = *(const float4*)(tp + HB);
    float4 tg_ = *(const float4*)(tp + 2 * HB);
    float4 to = *(const float4*)(tp + 3 * HB);
    float4 cp = *(const float4*)(c_prev + (size_t)b * H_DIM + j);

    float4 hv, cv;
    {
        float i_ = 1.f / (1.f + expf(-(gi.x + ti.x)));
        float f_ = 1.f / (1.f + expf(-(gf.x + tf.x)));
        float g_ = tanhf(gg.x + tg_.x);
        float o_ = 1.f / (1.f + expf(-(go.x + to.x)));
        cv.x = f_ * cp.x + i_ * g_;  hv.x = o_ * tanhf(cv.x);
    }
    {
        float i_ = 1.f / (1.f + expf(-(gi.y + ti.y)));
        float f_ = 1.f / (1.f + expf(-(gf.y + tf.y)));
        float g_ = tanhf(gg.y + tg_.y);
        float o_ = 1.f / (1.f + expf(-(go.y + to.y)));
        cv.y = f_ * cp.y + i_ * g_;  hv.y = o_ * tanhf(cv.y);
    }
    {
        float i_ = 1.f / (1.f + expf(-(gi.z + ti.z)));
        float f_ = 1.f / (1.f + expf(-(gf.z + tf.z)));
        float g_ = tanhf(gg.z + tg_.z);
        float o_ = 1.f / (1.f + expf(-(go.z + to.z)));
        cv.z = f_ * cp.z + i_ * g_;  hv.z = o_ * tanhf(cv.z);
    }
    {
        float i_ = 1.f / (1.f + expf(-(gi.w + ti.w)));
        float f_ = 1.f / (1.f + expf(-(gf.w + tf.w)));
        float g_ = tanhf(gg.w + tg_.w);
        float o_ = 1.f / (1.f + expf(-(go.w + to.w)));
        cv.w = f_ * cp.w + i_ * g_;  hv.w = o_ * tanhf(cv.w);
    }

    *(float4*)(out + (size_t)b * H_DIM + j) = hv;
    *(float4*)(out + (size_t)(B_SZ + b) * H_DIM + j) = cv;
}

// ---------------- launch ----------------
extern "C" void kernel_launch(void* const* d_in, const int* in_sizes, int n_in,
                              void* d_out, int out_size) {
    const float* x      = (const float*)d_in[0];
    const float* h_prev = (const float*)d_in[1];
    const float* c_prev = (const float*)d_in[2];
    const float* Win    = (const float*)d_in[3];
    const float* A      = (const float*)d_in[4];
    const float* Bm     = (const float*)d_in[5];
    float* out = (float*)d_out;

    void *p_x32, *p_h32, *p_s, *p_t;
    cudaGetSymbolAddress(&p_x32, g_x32);
    cudaGetSymbolAddress(&p_h32, g_h32);
    cudaGetSymbolAddress(&p_s, g_s);
    cudaGetSymbolAddress(&p_t, g_t);

    cudaFuncSetAttribute(gemm_fused_kernel, cudaFuncAttributeMaxDynamicSharedMemorySize,
                         GSMEM_BYTES);

    // launches ordered so ncu -s 5 captures gemm_fused_kernel (6th launch)
    // 1) block sums
    sum_blocks_kernel<<<B_SZ, HB>>>(h_prev);
    // 2) C32 = tf32(A - Bm)
    make_C_kernel<<<64, 256>>>(A, Bm);
    // 3) fp32 t = s @ Bm^T
    {
        dim3 grid(512 / 128, B_SZ / 128);
        gemm_nt_kernel<<<grid, 256>>>((const float*)p_s, Bm, (float*)p_t,
                                      HB, HB, HB, 4 * HB);
    }
    // 4-5) tf32-round x, h
    conv_tf32_kernel<<<(B_SZ * IN_DIM / 4) / 256, 256>>>(x, (float*)p_x32);
    conv_tf32_kernel<<<(B_SZ * H_DIM / 4) / 256, 256>>>(h_prev, (float*)p_h32);

    // 6) fused gates GEMM (main + struct) on tensor cores; W consumed raw
    {
        dim3 grid(G4H / BN, B_SZ / BM);
        gemm_fused_kernel<<<grid, 256, GSMEM_BYTES>>>(Win);
    }

    // 7) elementwise LSTM cell (+ t-term)
    lstm_elem_kernel<<<(B_SZ * H_DIM / 4) / 256, 256>>>(c_prev, out);
}